// round 13
// baseline (speedup 1.0000x reference)
#include <cuda_runtime.h>
#include <cuda_fp16.h>
#include <cstdint>
#include <math.h>

// DoubleNet (sm_103, HMMA): TOTAL fusion. One CTA carries a 64-sample m-block
// through pay net (frac -> registers), alloc net (mat -> SMEM f32 stage), and
// an in-CTA linear-domain Sinkhorn (4 threads/sample), writing allocs+payments
// directly. fp16 2-way-split HMMA products. B=32768, D=256, H=128, A=I=16.

#define MAXB 32768

__device__ __half g_wt[327680];   // per-weight: hi plane [N*K], lo plane [N*K]

// offsets in halves
#define OFF_AW0 0
#define OFF_AW1 65536
#define OFF_AW2 98304
#define OFF_AW3 131072
#define OFF_PW0 196608
#define OFF_PW1 262144
#define OFF_PW2 294912

// ---------------- helpers ----------------------------------------------------
__device__ __forceinline__ uint32_t smem_u32(const void* p) {
    uint32_t a;
    asm("{ .reg .u64 t; cvta.to.shared.u64 t, %1; cvt.u32.u64 %0, t; }"
        : "=r"(a) : "l"(p));
    return a;
}
__device__ __forceinline__ void split2(float x0, float x1, uint32_t& hw, uint32_t& lw) {
    __half h0 = __float2half_rn(x0), h1 = __float2half_rn(x1);
    __half l0 = __float2half_rn(x0 - __half2float(h0));
    __half l1 = __float2half_rn(x1 - __half2float(h1));
    hw = (uint32_t)__half_as_ushort(h0) | ((uint32_t)__half_as_ushort(h1) << 16);
    lw = (uint32_t)__half_as_ushort(l0) | ((uint32_t)__half_as_ushort(l1) << 16);
}
__device__ __forceinline__ void mma16816_f(float* d, const uint32_t* a, const uint32_t* b) {
    asm volatile(
        "mma.sync.aligned.m16n8k16.row.col.f32.f16.f16.f32 "
        "{%0,%1,%2,%3}, {%4,%5,%6,%7}, {%8,%9}, {%0,%1,%2,%3};"
        : "+f"(d[0]), "+f"(d[1]), "+f"(d[2]), "+f"(d[3])
        : "r"(a[0]), "r"(a[1]), "r"(a[2]), "r"(a[3]), "r"(b[0]), "r"(b[1]));
}
__device__ __forceinline__ void mma16816_h(uint32_t* d, const uint32_t* a, const uint32_t* b) {
    asm volatile(
        "mma.sync.aligned.m16n8k16.row.col.f16.f16.f16.f16 "
        "{%0,%1}, {%2,%3,%4,%5}, {%6,%7}, {%0,%1};"
        : "+r"(d[0]), "+r"(d[1])
        : "r"(a[0]), "r"(a[1]), "r"(a[2]), "r"(a[3]), "r"(b[0]), "r"(b[1]));
}
#define LDSM4(R, addr) \
    asm volatile("ldmatrix.sync.aligned.m8n8.x4.shared.b16 {%0,%1,%2,%3}, [%4];" \
                 : "=r"((R)[0]), "=r"((R)[1]), "=r"((R)[2]), "=r"((R)[3]) : "r"(addr))
#define CP_ASYNC16(dst, src) \
    asm volatile("cp.async.cg.shared.global [%0], [%1], 16;" :: "r"(dst), "l"(src))
#define CP_COMMIT() asm volatile("cp.async.commit_group;")
#define CP_WAIT0()  asm volatile("cp.async.wait_group 0;")

// ---------------- weight packing: SMEM tile transpose ------------------------
__global__ void pack_w_tile(const float* __restrict__ aw0, const float* __restrict__ aw1,
                            const float* __restrict__ aw2, const float* __restrict__ aw3,
                            const float* __restrict__ pw0, const float* __restrict__ pw1,
                            const float* __restrict__ pw2, __half* __restrict__ wt)
{
    const float* src; int K, N, off;
    switch (blockIdx.y) {
        case 0: src = aw0; K = 256; N = 128; off = OFF_AW0; break;
        case 1: src = aw1; K = 128; N = 128; off = OFF_AW1; break;
        case 2: src = aw2; K = 128; N = 128; off = OFF_AW2; break;
        case 3: src = aw3; K = 128; N = 256; off = OFF_AW3; break;
        case 4: src = pw0; K = 256; N = 128; off = OFF_PW0; break;
        case 5: src = pw1; K = 128; N = 128; off = OFF_PW1; break;
        default: src = pw2; K = 128; N = 128; off = OFF_PW2; break;
    }
    int tiles_n = N / 32;
    int tile = blockIdx.x;
    if (tile >= (K / 32) * tiles_n) return;
    int k0 = (tile / tiles_n) * 32, n0 = (tile % tiles_n) * 32;

    __shared__ float t[32][33];
    int c = threadIdx.x & 31, r8 = threadIdx.x >> 5;
#pragma unroll
    for (int j = 0; j < 4; j++) {
        int r = r8 + j * 8;
        t[r][c] = src[(size_t)(k0 + r) * N + n0 + c];   // coalesced read
    }
    __syncthreads();
#pragma unroll
    for (int j = 0; j < 4; j++) {
        int n = r8 + j * 8;
        float v = t[c][n];
        __half h = __float2half_rn(v);
        size_t o = (size_t)(n0 + n) * K + k0 + c;
        wt[off + o]                 = h;                 // coalesced write
        wt[off + (size_t)N * K + o] = __float2half_rn(v - __half2float(h));
    }
}

// ---------------- SMEM layout ------------------------------------------------
#define ROWB   272
#define APLANE 17408
#define SM_AHI 0
#define SM_ALO 17408
#define SM_BHI 34816
#define SM_BLO 69632
#define SMEM_BYTES 104448
#define STG_ROW 260   // f32 words per staged mat row

__device__ __forceinline__ void cpa128(uint32_t dst, const __half* __restrict__ src,
                                       int stride_h, int tid) {
#pragma unroll
    for (int j = 0; j < 8; j++) {
        int lin = j * 256 + tid;
        int row = lin >> 4;
        int q   = lin & 15;
        CP_ASYNC16(dst + row * ROWB + q * 16, src + row * stride_h + q * 8);
    }
}
__device__ __forceinline__ void load_w(uint32_t sb, const __half* __restrict__ whi,
                                       const __half* __restrict__ wlo,
                                       int noff, int koff, int K, int tid) {
    cpa128(sb + SM_BHI, whi + (size_t)noff * K + koff, K, tid);
    cpa128(sb + SM_BLO, wlo + (size_t)noff * K + koff, K, tid);
    CP_COMMIT();
}
__device__ __forceinline__ void load_f32_pair(char* hi, char* lo,
                                              const float4* __restrict__ src,
                                              int stride16, int tid) {
#pragma unroll
    for (int j = 0; j < 8; j++) {
        int lin = j * 256 + tid;
        int row = lin >> 5;
        int g   = lin & 31;
        float4 v = src[row * stride16 + g];
        uint32_t h0, l0, h1, l1;
        split2(v.x, v.y, h0, l0);
        split2(v.z, v.w, h1, l1);
        int off = row * ROWB + g * 8;
        *(uint2*)(hi + off) = make_uint2(h0, h1);
        *(uint2*)(lo + off) = make_uint2(l0, l1);
    }
}

// ---------------- MMA tile ----------------------------------------------------
struct Acc {
    float    f[2][4][4];
    uint32_t h[2][4][2];
    __device__ __forceinline__ void zero() {
#pragma unroll
        for (int i = 0; i < 2; i++)
#pragma unroll
            for (int j = 0; j < 4; j++) {
#pragma unroll
                for (int q = 0; q < 4; q++) f[i][j][q] = 0.f;
                h[i][j][0] = 0u; h[i][j][1] = 0u;
            }
    }
    __device__ __forceinline__ void merge() {
#pragma unroll
        for (int i = 0; i < 2; i++)
#pragma unroll
            for (int j = 0; j < 4; j++) {
                float2 f0 = __half22float2(*reinterpret_cast<__half2*>(&h[i][j][0]));
                float2 f1 = __half22float2(*reinterpret_cast<__half2*>(&h[i][j][1]));
                f[i][j][0] += f0.x; f[i][j][1] += f0.y;
                f[i][j][2] += f1.x; f[i][j][3] += f1.y;
            }
    }
};

__device__ __forceinline__ void mma_phase(Acc& A, uint32_t aBase, uint32_t bBase) {
#pragma unroll
    for (int kk = 0; kk < 8; kk++) {
        uint32_t ahi[2][4], alo[2][4];
#pragma unroll
        for (int i = 0; i < 2; i++) {
            LDSM4(ahi[i], aBase + i * (16 * ROWB) + kk * 32);
            LDSM4(alo[i], aBase + APLANE + i * (16 * ROWB) + kk * 32);
        }
        uint32_t bhi[4][2], blo[4][2];
#pragma unroll
        for (int jj = 0; jj < 2; jj++) {
            uint32_t r[4];
            LDSM4(r, bBase + jj * (16 * ROWB) + kk * 32);
            bhi[2 * jj][0] = r[0]; bhi[2 * jj + 1][0] = r[1];
            bhi[2 * jj][1] = r[2]; bhi[2 * jj + 1][1] = r[3];
            LDSM4(r, bBase + 2 * APLANE + jj * (16 * ROWB) + kk * 32);
            blo[2 * jj][0] = r[0]; blo[2 * jj + 1][0] = r[1];
            blo[2 * jj][1] = r[2]; blo[2 * jj + 1][1] = r[3];
        }
#pragma unroll
        for (int j = 0; j < 4; j++)
#pragma unroll
            for (int i = 0; i < 2; i++) {
                mma16816_f(A.f[i][j], ahi[i], bhi[j]);
                mma16816_h(A.h[i][j], ahi[i], blo[j]);
                mma16816_h(A.h[i][j], alo[i], bhi[j]);
            }
    }
}

__device__ __forceinline__ void epilogue_act(Acc& A, const float* __restrict__ bias,
                                             char* smem, int wm, int wn, int lane) {
    const int r4 = lane >> 2;
    uint32_t* stgH = (uint32_t*)(smem + SM_AHI);
    uint32_t* stgL = (uint32_t*)(smem + SM_ALO);
#pragma unroll
    for (int i = 0; i < 2; i++) {
        int r0 = wm + i * 16 + r4;
#pragma unroll
        for (int j = 0; j < 4; j++) {
            int c0 = wn + j * 8 + (lane & 3) * 2;
            float b0 = bias[c0], b1 = bias[c0 + 1];
            uint32_t hw, lw;
            split2(tanhf(A.f[i][j][0] + b0), tanhf(A.f[i][j][1] + b1), hw, lw);
            stgH[r0 * 68 + (c0 >> 1)] = hw;
            stgL[r0 * 68 + (c0 >> 1)] = lw;
            split2(tanhf(A.f[i][j][2] + b0), tanhf(A.f[i][j][3] + b1), hw, lw);
            stgH[(r0 + 8) * 68 + (c0 >> 1)] = hw;
            stgL[(r0 + 8) * 68 + (c0 >> 1)] = lw;
        }
    }
}

// L0(K=256) + L1 + L2 with tanh epilogues into the A region.
// wpre_*: optional weight prefetch issued during L2's epilogue.
__device__ __forceinline__ void net3(char* smem, uint32_t sb, uint32_t aBase, uint32_t bBase,
                                     const float* __restrict__ bidsblk,
                                     const __half* w0, const __half* w1, const __half* w2,
                                     const float* b0, const float* b1, const float* b2,
                                     const __half* wpre_hi, const __half* wpre_lo,
                                     int wm, int wn, int lane, int tid, Acc& acc)
{
    acc.zero();
#pragma unroll 1
    for (int c = 0; c < 2; c++) {
        load_w(sb, w0, w0 + 32768, 0, c * 128, 256, tid);
        load_f32_pair(smem + SM_AHI, smem + SM_ALO,
                      (const float4*)(bidsblk + c * 128), 64, tid);
        CP_WAIT0(); __syncthreads();
        mma_phase(acc, aBase, bBase);
        __syncthreads();
    }
    load_w(sb, w1, w1 + 16384, 0, 0, 128, tid);
    acc.merge();
    epilogue_act(acc, b0, smem, wm, wn, lane);
    CP_WAIT0(); __syncthreads();

    acc.zero();
    mma_phase(acc, aBase, bBase);
    __syncthreads();
    load_w(sb, w2, w2 + 16384, 0, 0, 128, tid);
    acc.merge();
    epilogue_act(acc, b1, smem, wm, wn, lane);
    CP_WAIT0(); __syncthreads();

    acc.zero();
    mma_phase(acc, aBase, bBase);
    __syncthreads();
    if (wpre_hi) load_w(sb, wpre_hi, wpre_lo, 0, 0, 128, tid);
    acc.merge();
    epilogue_act(acc, b2, smem, wm, wn, lane);
    if (wpre_hi) CP_WAIT0();
    __syncthreads();
}

// ---------------- the fully fused kernel --------------------------------------
// grid (M/64): one CTA per 64-sample m-block. 256 threads, 2 CTA/SM.
__global__ void __launch_bounds__(256, 2)
fused_all(const float* __restrict__ bids, const __half* __restrict__ wt,
          const float* __restrict__ ab0, const float* __restrict__ ab1,
          const float* __restrict__ ab2, const float* __restrict__ ab3,
          const float* __restrict__ pb0, const float* __restrict__ pb1,
          const float* __restrict__ pb2,
          const float* __restrict__ pw3, const float* __restrict__ pb3,
          float* __restrict__ outA, float* __restrict__ outP)
{
    extern __shared__ __align__(16) char smem[];
    const int tid  = threadIdx.x;
    const int lane = tid & 31;
    const int w    = tid >> 5;
    const int wm   = (w & 1) * 32;
    const int wn   = (w >> 1) * 32;
    const int bm   = blockIdx.x * 64;

    const uint32_t sb = smem_u32(smem);
    const int l15 = lane & 15;
    const int lhi = (lane >> 4) * 16;
    const uint32_t aBase = sb + SM_AHI + (uint32_t)(wm + l15) * ROWB + lhi;
    const uint32_t bBase = sb + SM_BHI + (uint32_t)(wn + l15) * ROWB + lhi;
    const float* bidsblk = bids + (size_t)bm * 256;

    Acc acc;

    // ================= PAY NET =================
    net3(smem, sb, aBase, bBase, bidsblk,
         wt + OFF_PW0, wt + OFF_PW1, wt + OFF_PW2,
         pb0, pb1, pb2, nullptr, nullptr, wm, wn, lane, tid, acc);

    // payment head -> frac kept in registers
    float fr4[4];
    {
        float* sW = (float*)(smem + SM_BHI);
#pragma unroll
        for (int t = 0; t < 8; t++) sW[t * 256 + tid] = pw3[t * 256 + tid];
        __syncthreads();
        const int s = tid >> 2, q = tid & 3;
        const __half* hh = (const __half*)(smem + SM_AHI) + s * 136;
        const __half* ll = (const __half*)(smem + SM_ALO) + s * 136;
        float a4[4];
#pragma unroll
        for (int j = 0; j < 4; j++) a4[j] = pb3[q * 4 + j];
#pragma unroll 8
        for (int k = 0; k < 128; k++) {
            float av = __half2float(hh[k]) + __half2float(ll[k]);
            const float* wr = sW + k * 16 + q * 4;
#pragma unroll
            for (int j = 0; j < 4; j++) a4[j] = fmaf(av, wr[j], a4[j]);
        }
#pragma unroll
        for (int j = 0; j < 4; j++)
            fr4[j] = __fdividef(1.f, 1.f + __expf(-a4[j]));
    }
    __syncthreads();

    // ================= ALLOC NET =================
    net3(smem, sb, aBase, bBase, bidsblk,
         wt + OFF_AW0, wt + OFF_AW1, wt + OFF_AW2,
         ab0, ab1, ab2, wt + OFF_AW3, wt + OFF_AW3 + 32768,
         wm, wn, lane, tid, acc);

    // ---- L3: N=256 in two halves, staged to SMEM f32 (never global) ----
    acc.zero();
    mma_phase(acc, aBase, bBase);           // half0 (cols 0..127)
    __syncthreads();
    load_w(sb, wt + OFF_AW3, wt + OFF_AW3 + 32768, 128, 0, 128, tid);
    acc.merge();
    float m0[2][4][4];
#pragma unroll
    for (int i = 0; i < 2; i++)
#pragma unroll
        for (int j = 0; j < 4; j++)
#pragma unroll
            for (int z = 0; z < 4; z++) m0[i][j][z] = acc.f[i][j][z];
    CP_WAIT0(); __syncthreads();
    acc.zero();
    mma_phase(acc, aBase, bBase);           // half1 (cols 128..255)
    __syncthreads();
    acc.merge();

    {   // stage mat = raw + ab3, 64 x 256 f32 at row stride STG_ROW
        float* stage = (float*)smem;
        const int r4l = lane >> 2;
#pragma unroll
        for (int i = 0; i < 2; i++) {
            int r0 = wm + i * 16 + r4l;
#pragma unroll
            for (int j = 0; j < 4; j++) {
                int c0 = wn + j * 8 + (lane & 3) * 2;
                float b0 = ab3[c0], b1 = ab3[c0 + 1];
                float b2 = ab3[128 + c0], b3 = ab3[128 + c0 + 1];
                stage[r0 * STG_ROW + c0]             = m0[i][j][0] + b0;
                stage[r0 * STG_ROW + c0 + 1]         = m0[i][j][1] + b1;
                stage[(r0 + 8) * STG_ROW + c0]       = m0[i][j][2] + b0;
                stage[(r0 + 8) * STG_ROW + c0 + 1]   = m0[i][j][3] + b1;
                stage[r0 * STG_ROW + 128 + c0]           = acc.f[i][j][0] + b2;
                stage[r0 * STG_ROW + 128 + c0 + 1]       = acc.f[i][j][1] + b3;
                stage[(r0 + 8) * STG_ROW + 128 + c0]     = acc.f[i][j][2] + b2;
                stage[(r0 + 8) * STG_ROW + 128 + c0 + 1] = acc.f[i][j][3] + b3;
            }
        }
    }
    __syncthreads();

    // ================= SINKHORN (4 threads/sample) =================
    {
        const int s = tid >> 2, q = tid & 3;
        const float* srow = (const float*)smem + s * STG_ROW;
        float Kx[16][4];
#pragma unroll
        for (int i = 0; i < 16; i++) {
            float4 x = *(const float4*)(srow + i * 16 + q * 4);
            Kx[i][0] = __expf(x.x * 10.f);
            Kx[i][1] = __expf(x.y * 10.f);
            Kx[i][2] = __expf(x.z * 10.f);
            Kx[i][3] = __expf(x.w * 10.f);
        }
        float v[4] = {1.f, 1.f, 1.f, 1.f}, v16 = 1.f;
        float u[16], u16;

#pragma unroll 1
        for (int rnd = 0; rnd < 40; rnd++) {
            float r[17];
#pragma unroll
            for (int i = 0; i < 16; i++) {
                float a = Kx[i][0] * v[0];
                a = fmaf(Kx[i][1], v[1], a);
                a = fmaf(Kx[i][2], v[2], a);
                a = fmaf(Kx[i][3], v[3], a);
                r[i] = a;
            }
            r[16] = v[0] + v[1] + v[2] + v[3];
#pragma unroll
            for (int i = 0; i < 17; i++) {
                r[i] += __shfl_xor_sync(0xFFFFFFFFu, r[i], 1);
                r[i] += __shfl_xor_sync(0xFFFFFFFFu, r[i], 2);
            }
#pragma unroll
            for (int i = 0; i < 16; i++) u[i] = __fdividef(1.f, r[i] + v16);
            u16 = __fdividef(16.f, r[16] + v16);

            float usum = u[0];
#pragma unroll
            for (int i = 1; i < 16; i++) usum += u[i];
#pragma unroll
            for (int j = 0; j < 4; j++) {
                float c = u16;
#pragma unroll
                for (int i = 0; i < 16; i++) c = fmaf(Kx[i][j], u[i], c);
                v[j] = __fdividef(1.f, c);
            }
            v16 = __fdividef(16.f, usum + u16);
        }

        // outputs: allocs (own 4 cols) + payments (frac held in fr4)
        const float* brow = bids + (size_t)(bm + s) * 256;
        float* arow = outA + (size_t)(bm + s) * 256;
        float pay4[4];
#pragma unroll
        for (int i = 0; i < 16; i++) {
            float4 bb = *(const float4*)(brow + i * 16 + q * 4);
            float ui = u[i];
            float a0 = ui * Kx[i][0] * v[0], a1 = ui * Kx[i][1] * v[1];
            float a2 = ui * Kx[i][2] * v[2], a3 = ui * Kx[i][3] * v[3];
            *(float4*)(arow + i * 16 + q * 4) = make_float4(a0, a1, a2, a3);
            float pp = a0 * bb.x + a1 * bb.y + a2 * bb.z + a3 * bb.w;
            pp += __shfl_xor_sync(0xFFFFFFFFu, pp, 1);
            pp += __shfl_xor_sync(0xFFFFFFFFu, pp, 2);
            if ((i >> 2) == q) pay4[i & 3] = pp * fr4[i & 3];
        }
        *(float4*)(outP + (size_t)(bm + s) * 16 + q * 4) =
            make_float4(pay4[0], pay4[1], pay4[2], pay4[3]);
    }
}

// ---------------- launch -----------------------------------------------------
extern "C" void kernel_launch(void* const* d_in, const int* in_sizes, int n_in,
                              void* d_out, int out_size)
{
    const float* bids = (const float*)d_in[0];
    const float* aw0 = (const float*)d_in[1];  const float* ab0 = (const float*)d_in[2];
    const float* aw1 = (const float*)d_in[3];  const float* ab1 = (const float*)d_in[4];
    const float* aw2 = (const float*)d_in[5];  const float* ab2 = (const float*)d_in[6];
    const float* aw3 = (const float*)d_in[7];  const float* ab3 = (const float*)d_in[8];
    const float* pw0 = (const float*)d_in[9];  const float* pb0 = (const float*)d_in[10];
    const float* pw1 = (const float*)d_in[11]; const float* pb1 = (const float*)d_in[12];
    const float* pw2 = (const float*)d_in[13]; const float* pb2 = (const float*)d_in[14];
    const float* pw3 = (const float*)d_in[15]; const float* pb3 = (const float*)d_in[16];

    const int M = in_sizes[0] / 256;  // 32768

    void* p;
    cudaGetSymbolAddress(&p, g_wt);   __half* wt = (__half*)p;

    cudaFuncSetAttribute(fused_all, cudaFuncAttributeMaxDynamicSharedMemorySize,
                         SMEM_BYTES);

    pack_w_tile<<<dim3(32, 7), 256>>>(aw0, aw1, aw2, aw3, pw0, pw1, pw2, wt);

    float* out = (float*)d_out;
    fused_all<<<M / 64, 256, SMEM_BYTES>>>(
        bids, wt, ab0, ab1, ab2, ab3, pb0, pb1, pb2, pw3, pb3,
        out, out + (size_t)M * 256);
}